// round 12
// baseline (speedup 1.0000x reference)
#include <cuda_runtime.h>
#include <cuda_fp16.h>
#include <cstdint>

#define B_   8
#define S_   1024
#define D_   2048
#define H_   16
#define DH_  128
#define FF_  8192
#define NTOK (B_*S_)   // 8192
#define LDQKV (3*D_)   // 6144

// ---------------- scratch ----------------
__device__ float    g_k[(size_t)NTOK * D_];           // fp32: Wo out / FFN2 out
__device__ float    g_v[(size_t)NTOK * D_];           // fp32: x1 exact
__device__ float    g_bqkv[3 * D_];                   // concat bias
__device__ uint32_t g_mb[(size_t)S_ * (S_ / 32)];     // bit-packed mask
__device__ __half   h_x  [(size_t)NTOK * D_];
__device__ __half   h_qkv[(size_t)NTOK * LDQKV];      // fused Q|K|V
__device__ __half   h_ao [(size_t)NTOK * D_];
__device__ __half   h_x1 [(size_t)NTOK * D_];
__device__ __half   h_w  [(size_t)(4 * D_ * D_ + 2 * FF_ * D_)];
__device__ __half   h_h  [(size_t)NTOK * FF_];        // fp16 FFN hidden

enum { EPI_NONE = 0, EPI_BIAS = 1, EPI_BIAS_RELU = 2 };

__device__ __forceinline__ uint32_t smem_u32(const void* p) {
    uint32_t a;
    asm("{ .reg .u64 t; cvta.to.shared.u64 t, %1; cvt.u32.u64 %0, t; }" : "=r"(a) : "l"(p));
    return a;
}

// ---------------- fp16 mma.sync GEMM (NT; A,B fp16; fp32 accum) ------------
// BK=128 chunks (256B smem rows, flash-attn swizzle), 2 stages, ONE sync/chunk.
template <int EPI, bool F16OUT>
__global__ void __launch_bounds__(256, 1) hgemm(
    const __half* __restrict__ A, int lda,
    const __half* __restrict__ Bm, int ldb,
    void* __restrict__ Cv, int ldc,
    int K, const float* __restrict__ bias)
{
    extern __shared__ __align__(16) char sm[];
    const int tid = threadIdx.x, lane = tid & 31, wid = tid >> 5;

    __half* Ch = (__half*)Cv;
    float*  Cf = (float*)Cv;

    const int rowBase = blockIdx.y * 128;
    const int colBase = blockIdx.x * 256;

    constexpr int ASTG = 128 * 256;  // bytes per A stage (256B rows, 128 halves)
    constexpr int BSTG = 256 * 256;
    const uint32_t sA0 = smem_u32(sm);
    const uint32_t sB0 = sA0 + 2 * ASTG;

    const int wm = (wid & 1) * 64;
    const int wn = (wid >> 1) * 64;
    const int g  = lane >> 2, qt = lane & 3;

    // ldmatrix per-lane addressing (256B rows; swizzle cs=(c&8)|((c&7)^(r&7)))
    const int aR = wm + ((lane >> 3) & 1) * 8 + (lane & 7);
    const int aHi = lane >> 4;               // 0/1 k-half within 32B pair
    const uint32_t aRow = sA0 + (uint32_t)aR * 256;
    const int aS = aR & 7;
    const int bR = wn + ((lane >> 4) << 3) + (lane & 7);
    const int bHi = (lane >> 3) & 1;
    const uint32_t bRow = sB0 + (uint32_t)bR * 256;
    const int bS = bR & 7;
    uint32_t cA[8], cB[8];
#pragma unroll
    for (int ks = 0; ks < 8; ks++) {
        int ca = 2 * ks + aHi, cb = 2 * ks + bHi;
        cA[ks] = (uint32_t)(((ca & 8) | ((ca & 7) ^ aS)) * 16);
        cB[ks] = (uint32_t)(((cb & 8) | ((cb & 7) ^ bS)) * 16);
    }

    float acc[4][8][4];
#pragma unroll
    for (int i = 0; i < 4; i++)
#pragma unroll
        for (int j = 0; j < 8; j++)
#pragma unroll
            for (int u = 0; u < 4; u++) acc[i][j][u] = 0.f;

    auto issue = [&](int kt, int buf) {
        const int k0 = kt << 7;
#pragma unroll
        for (int j = 0; j < 8; j++) {       // A: 128 rows x 16 chunks
            int f = tid + 256 * j; int r = f >> 4, c = f & 15;
            const __half* src = A + (long)(rowBase + r) * lda + k0 + c * 8;
            int cs = (c & 8) | ((c & 7) ^ (r & 7));
            uint32_t dst = sA0 + (uint32_t)(buf * ASTG + r * 256 + cs * 16);
            asm volatile("cp.async.cg.shared.global [%0], [%1], 16;" :: "r"(dst), "l"(src));
        }
#pragma unroll
        for (int j = 0; j < 16; j++) {      // B: 256 rows x 16 chunks
            int f = tid + 256 * j; int r = f >> 4, c = f & 15;
            const __half* src = Bm + (long)(colBase + r) * ldb + k0 + c * 8;
            int cs = (c & 8) | ((c & 7) ^ (r & 7));
            uint32_t dst = sB0 + (uint32_t)(buf * BSTG + r * 256 + cs * 16);
            asm volatile("cp.async.cg.shared.global [%0], [%1], 16;" :: "r"(dst), "l"(src));
        }
        asm volatile("cp.async.commit_group;");
    };

    auto compute = [&](int buf) {
        const uint32_t ab = aRow + (uint32_t)(buf * ASTG);
        const uint32_t bb = bRow + (uint32_t)(buf * BSTG);
#pragma unroll
        for (int ks = 0; ks < 8; ks++) {
            uint32_t af[4][4], bf[8][2];
#pragma unroll
            for (int i = 0; i < 4; i++)
                asm volatile("ldmatrix.sync.aligned.m8n8.x4.shared.b16 {%0,%1,%2,%3}, [%4];"
                    : "=r"(af[i][0]), "=r"(af[i][1]), "=r"(af[i][2]), "=r"(af[i][3])
                    : "r"(ab + i * 4096 + cA[ks]));
#pragma unroll
            for (int p = 0; p < 4; p++)
                asm volatile("ldmatrix.sync.aligned.m8n8.x4.shared.b16 {%0,%1,%2,%3}, [%4];"
                    : "=r"(bf[2 * p][0]), "=r"(bf[2 * p][1]),
                      "=r"(bf[2 * p + 1][0]), "=r"(bf[2 * p + 1][1])
                    : "r"(bb + p * 4096 + cB[ks]));
#pragma unroll
            for (int i = 0; i < 4; i++)
#pragma unroll
                for (int jn = 0; jn < 8; jn++)
                    asm volatile(
                        "mma.sync.aligned.m16n8k16.row.col.f32.f16.f16.f32 "
                        "{%0,%1,%2,%3}, {%4,%5,%6,%7}, {%8,%9}, {%0,%1,%2,%3};"
                        : "+f"(acc[i][jn][0]), "+f"(acc[i][jn][1]),
                          "+f"(acc[i][jn][2]), "+f"(acc[i][jn][3])
                        : "r"(af[i][0]), "r"(af[i][1]), "r"(af[i][2]), "r"(af[i][3]),
                          "r"(bf[jn][0]), "r"(bf[jn][1]));
        }
    };

    const int NTL = K >> 7;
    issue(0, 0);
    for (int kt = 0; kt < NTL; kt++) {
        asm volatile("cp.async.wait_group 0;" ::: "memory");   // chunk kt arrived
        __syncthreads();                                       // + compute(kt-1) done
        if (kt + 1 < NTL) issue(kt + 1, (kt + 1) & 1);         // overlaps compute(kt)
        compute(kt & 1);
    }

    // ---- epilogue ----
#pragma unroll
    for (int i = 0; i < 4; i++) {
        const int row0 = rowBase + wm + i * 16 + g;
#pragma unroll
        for (int jn = 0; jn < 8; jn++) {
            const int col = colBase + wn + jn * 8 + qt * 2;
#pragma unroll
            for (int h = 0; h < 2; h++) {
                const int r = row0 + h * 8;
                float v0 = acc[i][jn][h * 2], v1 = acc[i][jn][h * 2 + 1];
                if (EPI == EPI_BIAS) {
                    v0 += bias[col]; v1 += bias[col + 1];
                } else if (EPI == EPI_BIAS_RELU) {
                    v0 = fmaxf(v0 + bias[col], 0.f);
                    v1 = fmaxf(v1 + bias[col + 1], 0.f);
                }
                if (F16OUT) {
                    *(__half2*)(Ch + (long)r * ldc + col) = __floats2half2_rn(v0, v1);
                } else {
                    float2 o; o.x = v0; o.y = v1;
                    *(float2*)(Cf + (long)r * ldc + col) = o;
                }
            }
        }
    }
}

// ---------------- flash attention (bit-packed mask, exp2/f16x2 softmax) ----
// scale passed pre-multiplied by log2(e): scores live in log2 domain.
__global__ void __launch_bounds__(256, 1) flash_attn(
    const __half* __restrict__ Qg, const __half* __restrict__ Kg,
    const __half* __restrict__ Vg, int ldq,
    const uint32_t* __restrict__ mbits,
    __half* __restrict__ Og, float scale2)
{
    extern __shared__ __align__(16) char sm[];
    const int tid = threadIdx.x, lane = tid & 31, wid = tid >> 5;
    const int g = lane >> 2, qt = lane & 3;
    const int qb = blockIdx.x, bh = blockIdx.y;
    const int b = bh >> 4, h = bh & 15;
    const size_t base = ((size_t)b * S_) * ldq + (size_t)h * DH_;
    const int q0 = qb * 128;

    const uint32_t sQ = smem_u32(sm);
    const uint32_t sK = sQ + 32768;
    const uint32_t sV = sK + 2 * 32768;

    auto ldtile = [&](uint32_t dst, const __half* src) {
#pragma unroll
        for (int j = 0; j < 8; j++) {
            int f = tid + 256 * j, r = f >> 4, c = f & 15;
            int cs = (c & 8) | ((c & 7) ^ (r & 7));
            const __half* s = src + (size_t)r * ldq + c * 8;
            uint32_t d = dst + r * 256 + cs * 16;
            asm volatile("cp.async.cg.shared.global [%0], [%1], 16;" :: "r"(d), "l"(s));
        }
    };

    ldtile(sQ, Qg + base + (size_t)q0 * ldq);
    ldtile(sK, Kg + base);
    ldtile(sV, Vg + base);
    asm volatile("cp.async.commit_group;");
    ldtile(sK + 32768, Kg + base + (size_t)128 * ldq);
    ldtile(sV + 32768, Vg + base + (size_t)128 * ldq);
    asm volatile("cp.async.commit_group;");

    uint32_t afq[8][4];
    {
        asm volatile("cp.async.wait_group 1;" ::: "memory");
        __syncthreads();
        const int ar = wid * 16 + ((lane >> 3) & 1) * 8 + (lane & 7);
#pragma unroll
        for (int ks = 0; ks < 8; ks++) {
            int c = ks * 2 + (lane >> 4);
            int cs = (c & 8) | ((c & 7) ^ (ar & 7));
            asm volatile("ldmatrix.sync.aligned.m8n8.x4.shared.b16 {%0,%1,%2,%3}, [%4];"
                : "=r"(afq[ks][0]), "=r"(afq[ks][1]), "=r"(afq[ks][2]), "=r"(afq[ks][3])
                : "r"(sQ + ar * 256 + cs * 16));
        }
    }

    float acc_o[16][4];
#pragma unroll
    for (int p = 0; p < 16; p++)
#pragma unroll
        for (int u = 0; u < 4; u++) acc_o[p][u] = 0.f;
    float m0 = -3.4e38f, m1 = -3.4e38f, l0 = 0.f, l1 = 0.f;

    const int r0g = q0 + wid * 16 + g;
    const uint32_t* mb0 = mbits + (size_t)r0g * (S_ / 32);
    const uint32_t* mb1 = mbits + (size_t)(r0g + 8) * (S_ / 32);

    for (int t = 0; t < 8; t++) {
        if (t == 7) asm volatile("cp.async.wait_group 0;" ::: "memory");
        else        asm volatile("cp.async.wait_group 1;" ::: "memory");
        __syncthreads();

        const uint32_t kbuf = sK + (t & 1) * 32768;
        const uint32_t vbuf = sV + (t & 1) * 32768;

        // ---- S = Q @ K^T ----
        float sa[16][4];
#pragma unroll
        for (int p = 0; p < 16; p++)
#pragma unroll
            for (int u = 0; u < 4; u++) sa[p][u] = 0.f;
#pragma unroll
        for (int ks = 0; ks < 8; ks++) {
#pragma unroll
            for (int p = 0; p < 8; p++) {
                int br = p * 16 + ((lane >> 4) << 3) + (lane & 7);
                int c = ks * 2 + ((lane >> 3) & 1);
                int cs = (c & 8) | ((c & 7) ^ (br & 7));
                uint32_t b0, b1, b2, b3;
                asm volatile("ldmatrix.sync.aligned.m8n8.x4.shared.b16 {%0,%1,%2,%3}, [%4];"
                    : "=r"(b0), "=r"(b1), "=r"(b2), "=r"(b3)
                    : "r"(kbuf + br * 256 + cs * 16));
                asm volatile(
                    "mma.sync.aligned.m16n8k16.row.col.f32.f16.f16.f32 "
                    "{%0,%1,%2,%3}, {%4,%5,%6,%7}, {%8,%9}, {%0,%1,%2,%3};"
                    : "+f"(sa[2*p][0]), "+f"(sa[2*p][1]), "+f"(sa[2*p][2]), "+f"(sa[2*p][3])
                    : "r"(afq[ks][0]), "r"(afq[ks][1]), "r"(afq[ks][2]), "r"(afq[ks][3]),
                      "r"(b0), "r"(b1));
                asm volatile(
                    "mma.sync.aligned.m16n8k16.row.col.f32.f16.f16.f32 "
                    "{%0,%1,%2,%3}, {%4,%5,%6,%7}, {%8,%9}, {%0,%1,%2,%3};"
                    : "+f"(sa[2*p+1][0]), "+f"(sa[2*p+1][1]), "+f"(sa[2*p+1][2]), "+f"(sa[2*p+1][3])
                    : "r"(afq[ks][0]), "r"(afq[ks][1]), "r"(afq[ks][2]), "r"(afq[ks][3]),
                      "r"(b2), "r"(b3));
            }
        }

        // ---- mask (bits) + scale (log2 domain) + online softmax ----
        const uint4 w0 = *(const uint4*)(mb0 + t * 4);
        const uint4 w1 = *(const uint4*)(mb1 + t * 4);
        const uint32_t w0a[4] = {w0.x, w0.y, w0.z, w0.w};
        const uint32_t w1a[4] = {w1.x, w1.y, w1.z, w1.w};
        float tm0 = -3.4e38f, tm1 = -3.4e38f;
#pragma unroll
        for (int j = 0; j < 16; j++) {
            const int sh = (j & 3) * 8 + qt * 2, wi = j >> 2;
            sa[j][0] = ((w0a[wi] >> sh)       & 1) ? sa[j][0] * scale2 : -1e9f;
            sa[j][1] = ((w0a[wi] >> (sh + 1)) & 1) ? sa[j][1] * scale2 : -1e9f;
            sa[j][2] = ((w1a[wi] >> sh)       & 1) ? sa[j][2] * scale2 : -1e9f;
            sa[j][3] = ((w1a[wi] >> (sh + 1)) & 1) ? sa[j][3] * scale2 : -1e9f;
            tm0 = fmaxf(tm0, fmaxf(sa[j][0], sa[j][1]));
            tm1 = fmaxf(tm1, fmaxf(sa[j][2], sa[j][3]));
        }
        tm0 = fmaxf(tm0, __shfl_xor_sync(0xffffffffu, tm0, 1));
        tm0 = fmaxf(tm0, __shfl_xor_sync(0xffffffffu, tm0, 2));
        tm1 = fmaxf(tm1, __shfl_xor_sync(0xffffffffu, tm1, 1));
        tm1 = fmaxf(tm1, __shfl_xor_sync(0xffffffffu, tm1, 2));
        const float mn0 = fmaxf(m0, tm0), mn1 = fmaxf(m1, tm1);
        const float al0 = exp2f(m0 - mn0), al1 = exp2f(m1 - mn1);
        m0 = mn0; m1 = mn1;

        // P = exp2(S - m) computed directly in fp16 pairs (half the MUFU ops);
        // row sums taken from the same fp16 values (consistent with PV MMA).
        float ts0 = 0.f, ts1 = 0.f;
        uint32_t pa[8][4];
#pragma unroll
        for (int j2 = 0; j2 < 8; j2++) {
            __half2 d0 = __floats2half2_rn(sa[2*j2][0]   - mn0, sa[2*j2][1]   - mn0);
            __half2 d1 = __floats2half2_rn(sa[2*j2][2]   - mn1, sa[2*j2][3]   - mn1);
            __half2 d2 = __floats2half2_rn(sa[2*j2+1][0] - mn0, sa[2*j2+1][1] - mn0);
            __half2 d3 = __floats2half2_rn(sa[2*j2+1][2] - mn1, sa[2*j2+1][3] - mn1);
            __half2 e0 = h2exp2(d0), e1 = h2exp2(d1);
            __half2 e2 = h2exp2(d2), e3 = h2exp2(d3);
            pa[j2][0] = *(uint32_t*)&e0; pa[j2][1] = *(uint32_t*)&e1;
            pa[j2][2] = *(uint32_t*)&e2; pa[j2][3] = *(uint32_t*)&e3;
            float2 f0 = __half22float2(e0), f1 = __half22float2(e1);
            float2 f2 = __half22float2(e2), f3 = __half22float2(e3);
            ts0 += f0.x + f0.y + f2.x + f2.y;
            ts1 += f1.x + f1.y + f3.x + f3.y;
        }
        ts0 += __shfl_xor_sync(0xffffffffu, ts0, 1);
        ts0 += __shfl_xor_sync(0xffffffffu, ts0, 2);
        ts1 += __shfl_xor_sync(0xffffffffu, ts1, 1);
        ts1 += __shfl_xor_sync(0xffffffffu, ts1, 2);
        l0 = l0 * al0 + ts0;
        l1 = l1 * al1 + ts1;
#pragma unroll
        for (int p = 0; p < 16; p++) {
            acc_o[p][0] *= al0; acc_o[p][1] *= al0;
            acc_o[p][2] *= al1; acc_o[p][3] *= al1;
        }

        // ---- O += P @ V ----
#pragma unroll
        for (int ks = 0; ks < 8; ks++) {
#pragma unroll
            for (int p = 0; p < 8; p++) {
                int vr = ks * 16 + ((lane >> 3) & 1) * 8 + (lane & 7);
                int c = p * 2 + ((lane >> 4) & 1);
                int cs = (c & 8) | ((c & 7) ^ (vr & 7));
                uint32_t b0, b1, b2, b3;
                asm volatile("ldmatrix.sync.aligned.m8n8.x4.trans.shared.b16 {%0,%1,%2,%3}, [%4];"
                    : "=r"(b0), "=r"(b1), "=r"(b2), "=r"(b3)
                    : "r"(vbuf + vr * 256 + cs * 16));
                asm volatile(
                    "mma.sync.aligned.m16n8k16.row.col.f32.f16.f16.f32 "
                    "{%0,%1,%2,%3}, {%4,%5,%6,%7}, {%8,%9}, {%0,%1,%2,%3};"
                    : "+f"(acc_o[2*p][0]), "+f"(acc_o[2*p][1]), "+f"(acc_o[2*p][2]), "+f"(acc_o[2*p][3])
                    : "r"(pa[ks][0]), "r"(pa[ks][1]), "r"(pa[ks][2]), "r"(pa[ks][3]),
                      "r"(b0), "r"(b1));
                asm volatile(
                    "mma.sync.aligned.m16n8k16.row.col.f32.f16.f16.f32 "
                    "{%0,%1,%2,%3}, {%4,%5,%6,%7}, {%8,%9}, {%0,%1,%2,%3};"
                    : "+f"(acc_o[2*p+1][0]), "+f"(acc_o[2*p+1][1]), "+f"(acc_o[2*p+1][2]), "+f"(acc_o[2*p+1][3])
                    : "r"(pa[ks][0]), "r"(pa[ks][1]), "r"(pa[ks][2]), "r"(pa[ks][3]),
                      "r"(b2), "r"(b3));
            }
        }

        __syncthreads();
        if (t + 2 < 8) {
            ldtile(sK + (t & 1) * 32768, Kg + base + (size_t)(t + 2) * 128 * ldq);
            ldtile(sV + (t & 1) * 32768, Vg + base + (size_t)(t + 2) * 128 * ldq);
            asm volatile("cp.async.commit_group;");
        }
    }

    // ---- epilogue: normalize, write fp16 (O stride = D_) ----
    const float i0 = 1.f / l0, i1 = 1.f / l1;
    const size_t obase = ((size_t)b * S_) * D_ + (size_t)h * DH_;
    __half* orow0 = Og + obase + (size_t)(q0 + wid * 16 + g) * D_;
    __half* orow1 = orow0 + (size_t)8 * D_;
#pragma unroll
    for (int p = 0; p < 16; p++) {
        const int col = p * 8 + qt * 2;
        *(__half2*)(orow0 + col) = __floats2half2_rn(acc_o[p][0] * i0, acc_o[p][1] * i0);
        *(__half2*)(orow1 + col) = __floats2half2_rn(acc_o[p][2] * i1, acc_o[p][3] * i1);
    }
}

// ---------------- prep kernels ---------------------------------------------
// f2h: 2 independent streams per thread (MLP 4) for higher HBM utilization.
__global__ void __launch_bounds__(256) f2h(
    const float4* __restrict__ in, uint4* __restrict__ out, int n8)
{
    const int half_n = n8 >> 1;
    int i = blockIdx.x * blockDim.x + threadIdx.x;
    if (i < half_n) {
        float4 a0 = in[2 * i], b0 = in[2 * i + 1];
        float4 a1 = in[2 * (i + half_n)], b1 = in[2 * (i + half_n) + 1];
        __half2 q0 = __floats2half2_rn(a0.x, a0.y), q1 = __floats2half2_rn(a0.z, a0.w);
        __half2 q2 = __floats2half2_rn(b0.x, b0.y), q3 = __floats2half2_rn(b0.z, b0.w);
        __half2 r0 = __floats2half2_rn(a1.x, a1.y), r1 = __floats2half2_rn(a1.z, a1.w);
        __half2 r2 = __floats2half2_rn(b1.x, b1.y), r3 = __floats2half2_rn(b1.z, b1.w);
        uint4 u, v;
        u.x = *(uint32_t*)&q0; u.y = *(uint32_t*)&q1;
        u.z = *(uint32_t*)&q2; u.w = *(uint32_t*)&q3;
        v.x = *(uint32_t*)&r0; v.y = *(uint32_t*)&r1;
        v.z = *(uint32_t*)&r2; v.w = *(uint32_t*)&r3;
        out[i] = u;
        out[i + half_n] = v;
    }
}

// pack_mask: one coalesced LDG per thread + ballot.
__global__ void __launch_bounds__(256) pack_mask(
    const int* __restrict__ m, uint32_t* __restrict__ mb)
{
    int gw = (blockIdx.x * blockDim.x + threadIdx.x) >> 5;
    int lane = threadIdx.x & 31;
    int v = m[(size_t)gw * 32 + lane];
    uint32_t bits = __ballot_sync(0xffffffffu, v != 0);
    if (lane == 0) mb[gw] = bits;
}

// ---------------- fused residual + LayerNorm -------------------------------
__device__ __forceinline__ float blk_sum(float v, float* sh)
{
#pragma unroll
    for (int o = 16; o; o >>= 1) v += __shfl_xor_sync(0xffffffffu, v, o);
    const int lane = threadIdx.x & 31, w = threadIdx.x >> 5;
    if (lane == 0) sh[w] = v;
    __syncthreads();
    if (w == 0) {
        float t = (lane < 8) ? sh[lane] : 0.f;
#pragma unroll
        for (int o = 4; o; o >>= 1) t += __shfl_xor_sync(0xffu, t, o);
        if (lane == 0) sh[0] = t;
    }
    __syncthreads();
    const float r = sh[0];
    __syncthreads();
    return r;
}

template <bool DUAL>
__global__ void __launch_bounds__(256) ln_kernel(
    const float* __restrict__ a, const float* __restrict__ b,
    const float* __restrict__ g, const float* __restrict__ be,
    float* __restrict__ out, __half* __restrict__ out_h)
{
    __shared__ float sh[8];
    const int row = blockIdx.x, tid = threadIdx.x;
    const float* pa = a + (size_t)row * D_;
    const float* pb = b + (size_t)row * D_;
    const int c0 = tid * 8;

    float x[8];
    {
        float4 a0 = *(const float4*)&pa[c0], a1 = *(const float4*)&pa[c0 + 4];
        float4 b0 = *(const float4*)&pb[c0], b1 = *(const float4*)&pb[c0 + 4];
        x[0] = a0.x + b0.x; x[1] = a0.y + b0.y; x[2] = a0.z + b0.z; x[3] = a0.w + b0.w;
        x[4] = a1.x + b1.x; x[5] = a1.y + b1.y; x[6] = a1.z + b1.z; x[7] = a1.w + b1.w;
    }
    float s = 0.f;
#pragma unroll
    for (int i = 0; i < 8; i++) s += x[i];
    const float mean = blk_sum(s, sh) * (1.f / D_);

    float vs = 0.f;
#pragma unroll
    for (int i = 0; i < 8; i++) { const float d = x[i] - mean; vs += d * d; }
    const float var = blk_sum(vs, sh) * (1.f / D_);
    const float inv = rsqrtf(var + 1e-5f);

    float o[8];
    float4 g0 = *(const float4*)&g[c0],  g1v = *(const float4*)&g[c0 + 4];
    float4 e0 = *(const float4*)&be[c0], e1v = *(const float4*)&be[c0 + 4];
    o[0] = (x[0] - mean) * inv * g0.x + e0.x;
    o[1] = (x[1] - mean) * inv * g0.y + e0.y;
    o[2] = (x[2] - mean) * inv * g0.z + e0.z;
    o[3] = (x[3] - mean) * inv * g0.w + e0.w;
    o[4] = (x[4] - mean) * inv * g1v.x + e1v.x;
    o[5] = (x[5] - mean) * inv * g1v.y + e1v.y;
    o[6] = (x[6] - mean) * inv * g1v.z + e1v.z;
    o[7] = (x[7] - mean) * inv * g1v.w + e1v.w;

    float* po = out + (size_t)row * D_;
    *(float4*)&po[c0]     = *(float4*)&o[0];
    *(float4*)&po[c0 + 4] = *(float4*)&o[4];
    if (DUAL) {
        __half2* ph = (__half2*)(out_h + (size_t)row * D_ + c0);
        ph[0] = __floats2half2_rn(o[0], o[1]);
        ph[1] = __floats2half2_rn(o[2], o[3]);
        ph[2] = __floats2half2_rn(o[4], o[5]);
        ph[3] = __floats2half2_rn(o[6], o[7]);
    }
}

// ---------------- launch ----------------------------------------------------
extern "C" void kernel_launch(void* const* d_in, const int* in_sizes, int n_in,
                              void* d_out, int out_size)
{
    const float* x    = (const float*)d_in[0];
    const int*   mask = (const int*)  d_in[1];
    const float* Wq = (const float*)d_in[2];  const float* bq = (const float*)d_in[3];
    const float* Wk = (const float*)d_in[4];  const float* bk = (const float*)d_in[5];
    const float* Wv = (const float*)d_in[6];  const float* bv = (const float*)d_in[7];
    const float* Wo = (const float*)d_in[8];  const float* bo = (const float*)d_in[9];
    const float* W1 = (const float*)d_in[10]; const float* b1 = (const float*)d_in[11];
    const float* W2 = (const float*)d_in[12]; const float* b2 = (const float*)d_in[13];
    const float* g1 = (const float*)d_in[14]; const float* be1 = (const float*)d_in[15];
    const float* g2 = (const float*)d_in[16]; const float* be2 = (const float*)d_in[17];
    float* out = (float*)d_out;

    float *ko, *x1, *bqkv;
    uint32_t* mb;
    __half *hx, *hqkv, *hao, *hx1, *hw, *hh;
    cudaGetSymbolAddress((void**)&ko,   g_k);
    cudaGetSymbolAddress((void**)&x1,   g_v);
    cudaGetSymbolAddress((void**)&bqkv, g_bqkv);
    cudaGetSymbolAddress((void**)&mb,   g_mb);
    cudaGetSymbolAddress((void**)&hx,   h_x);
    cudaGetSymbolAddress((void**)&hqkv, h_qkv);
    cudaGetSymbolAddress((void**)&hao,  h_ao);
    cudaGetSymbolAddress((void**)&hx1,  h_x1);
    cudaGetSymbolAddress((void**)&hw,   h_w);
    cudaGetSymbolAddress((void**)&hh,   h_h);

    __half* hWqkv = hw;                               // Wq|Wk|Wv contiguous
    __half* hWo = hw + (size_t)3 * D_ * D_;
    __half* hW1 = hw + (size_t)4 * D_ * D_;
    __half* hW2 = hW1 + (size_t)FF_ * D_;

    const int SMEM   = 2 * (128 * 256 + 256 * 256);   // 196608
    const int SMEM_FA = 5 * 32768;                    // 163840
    cudaFuncSetAttribute(hgemm<EPI_BIAS, true>,
                         cudaFuncAttributeMaxDynamicSharedMemorySize, SMEM);
    cudaFuncSetAttribute(hgemm<EPI_BIAS, false>,
                         cudaFuncAttributeMaxDynamicSharedMemorySize, SMEM);
    cudaFuncSetAttribute(hgemm<EPI_BIAS_RELU, true>,
                         cudaFuncAttributeMaxDynamicSharedMemorySize, SMEM);
    cudaFuncSetAttribute(flash_attn,
                         cudaFuncAttributeMaxDynamicSharedMemorySize, SMEM_FA);

    const float scale  = 0.08838834764831843f;         // 1/sqrt(128)
    const float scale2 = scale * 1.4426950408889634f;  // * log2(e)

    // ---- prep: fp16 conversions, bias concat, mask pack ----
    auto cv = [&](const float* src, __half* dst, size_t n) {
        int n8 = (int)(n / 8);
        f2h<<<(n8 / 2 + 255) / 256, 256>>>((const float4*)src, (uint4*)dst, n8);
    };
    cv(x,  hx,               (size_t)NTOK * D_);
    cv(Wq, hWqkv,            (size_t)D_ * D_);
    cv(Wk, hWqkv + (size_t)D_ * D_,     (size_t)D_ * D_);
    cv(Wv, hWqkv + (size_t)2 * D_ * D_, (size_t)D_ * D_);
    cv(Wo, hWo,              (size_t)D_ * D_);
    cv(W1, hW1,              (size_t)FF_ * D_);
    cv(W2, hW2,              (size_t)D_ * FF_);
    cudaMemcpyAsync(bqkv,          bq, D_ * sizeof(float), cudaMemcpyDeviceToDevice);
    cudaMemcpyAsync(bqkv + D_,     bk, D_ * sizeof(float), cudaMemcpyDeviceToDevice);
    cudaMemcpyAsync(bqkv + 2 * D_, bv, D_ * sizeof(float), cudaMemcpyDeviceToDevice);
    pack_mask<<<(S_ * S_) / 256, 256>>>(mask, mb);

    // ---- fused QKV projection: [8192, 6144] ----
    dim3 gqkv(LDQKV / 256, NTOK / 128, 1);
    hgemm<EPI_BIAS, true><<<gqkv, 256, SMEM>>>(
        hx, D_, hWqkv, D_, hqkv, LDQKV, D_, bqkv);

    // ---- fused attention (Q at +0, K at +D_, V at +2*D_ elements) ----
    flash_attn<<<dim3(S_ / 128, B_ * H_), 256, SMEM_FA>>>(
        hqkv, hqkv + D_, hqkv + 2 * D_, LDQKV, mb, hao, scale2);

    // ---- output projection (fp32 out), LN1 (dual out) ----
    dim3 gproj(D_ / 256, NTOK / 128, 1);
    hgemm<EPI_BIAS, false><<<gproj, 256, SMEM>>>(
        hao, D_, hWo, D_, ko, D_, D_, bo);
    ln_kernel<true><<<NTOK, 256>>>(ko, x, g1, be1, x1, hx1);

    // ---- FFN ----
    dim3 gff1(FF_ / 256, NTOK / 128, 1);
    hgemm<EPI_BIAS_RELU, true><<<gff1, 256, SMEM>>>(
        hx1, D_, hW1, D_, hh, FF_, D_, b1);
    hgemm<EPI_BIAS, false><<<gproj, 256, SMEM>>>(
        hh, FF_, hW2, FF_, ko, D_, FF_, b2);

    // ---- LN2 -> out ----
    ln_kernel<false><<<NTOK, 256>>>(ko, x1, g2, be2, out, nullptr);
}

// round 13
// speedup vs baseline: 1.0123x; 1.0123x over previous
#include <cuda_runtime.h>
#include <cuda_fp16.h>
#include <cstdint>

#define B_   8
#define S_   1024
#define D_   2048
#define H_   16
#define DH_  128
#define FF_  8192
#define NTOK (B_*S_)   // 8192
#define LDQKV (3*D_)   // 6144

// ---------------- scratch ----------------
__device__ float    g_k[(size_t)NTOK * D_];           // fp32: Wo out / FFN2 out
__device__ float    g_v[(size_t)NTOK * D_];           // fp32: x1 exact
__device__ float    g_bqkv[3 * D_];                   // concat bias
__device__ uint32_t g_mb[(size_t)S_ * (S_ / 32)];     // bit-packed mask
__device__ __half   h_x  [(size_t)NTOK * D_];
__device__ __half   h_qkv[(size_t)NTOK * LDQKV];      // fused Q|K|V
__device__ __half   h_ao [(size_t)NTOK * D_];
__device__ __half   h_x1 [(size_t)NTOK * D_];
__device__ __half   h_w  [(size_t)(4 * D_ * D_ + 2 * FF_ * D_)];
__device__ __half   h_h  [(size_t)NTOK * FF_];        // fp16 FFN hidden

enum { EPI_NONE = 0, EPI_BIAS = 1, EPI_BIAS_RELU = 2 };

__device__ __forceinline__ uint32_t smem_u32(const void* p) {
    uint32_t a;
    asm("{ .reg .u64 t; cvta.to.shared.u64 t, %1; cvt.u32.u64 %0, t; }" : "=r"(a) : "l"(p));
    return a;
}

// ---------------- fp16 mma.sync GEMM (NT; A,B fp16; fp32 accum) ------------
// BK=128 chunks (256B smem rows), 2 stages, ONE sync/chunk. BN = 256 or 128.
template <int BN, int EPI, bool F16OUT>
__global__ void __launch_bounds__(256, 1) hgemm(
    const __half* __restrict__ A, int lda,
    const __half* __restrict__ Bm, int ldb,
    void* __restrict__ Cv, int ldc,
    int K, const float* __restrict__ bias)
{
    extern __shared__ __align__(16) char sm[];
    const int tid = threadIdx.x, lane = tid & 31, wid = tid >> 5;

    __half* Ch = (__half*)Cv;
    float*  Cf = (float*)Cv;

    const int rowBase = blockIdx.y * 128;
    const int colBase = blockIdx.x * BN;

    constexpr int WN  = BN / 4;      // warp N tile (64 or 32)
    constexpr int JN  = WN / 8;      // 8 or 4
    constexpr int JP  = JN / 2;      // ldmatrix x4 pairs for B (4 or 2)
    constexpr int ASTG = 128 * 256;  // bytes per A stage (256B rows, 128 halves)
    constexpr int BSTG = BN * 256;
    const uint32_t sA0 = smem_u32(sm);
    const uint32_t sB0 = sA0 + 2 * ASTG;

    const int wm = (wid & 1) * 64;
    const int wn = (wid >> 1) * WN;
    const int g  = lane >> 2, qt = lane & 3;

    // ldmatrix per-lane addressing (256B rows; swizzle cs=(c&8)|((c&7)^(r&7)))
    const int aR = wm + ((lane >> 3) & 1) * 8 + (lane & 7);
    const int aHi = lane >> 4;               // 0/1 k-half within 32B pair
    const uint32_t aRow = sA0 + (uint32_t)aR * 256;
    const int aS = aR & 7;
    const int bR = wn + ((lane >> 4) << 3) + (lane & 7);
    const int bHi = (lane >> 3) & 1;
    const uint32_t bRow = sB0 + (uint32_t)bR * 256;
    const int bS = bR & 7;
    uint32_t cA[8], cB[8];
#pragma unroll
    for (int ks = 0; ks < 8; ks++) {
        int ca = 2 * ks + aHi, cb = 2 * ks + bHi;
        cA[ks] = (uint32_t)(((ca & 8) | ((ca & 7) ^ aS)) * 16);
        cB[ks] = (uint32_t)(((cb & 8) | ((cb & 7) ^ bS)) * 16);
    }

    float acc[4][JN][4];
#pragma unroll
    for (int i = 0; i < 4; i++)
#pragma unroll
        for (int j = 0; j < JN; j++)
#pragma unroll
            for (int u = 0; u < 4; u++) acc[i][j][u] = 0.f;

    auto issue = [&](int kt, int buf) {
        const int k0 = kt << 7;
#pragma unroll
        for (int j = 0; j < 8; j++) {          // A: 128 rows x 16 chunks
            int f = tid + 256 * j; int r = f >> 4, c = f & 15;
            const __half* src = A + (long)(rowBase + r) * lda + k0 + c * 8;
            int cs = (c & 8) | ((c & 7) ^ (r & 7));
            uint32_t dst = sA0 + (uint32_t)(buf * ASTG + r * 256 + cs * 16);
            asm volatile("cp.async.cg.shared.global [%0], [%1], 16;" :: "r"(dst), "l"(src));
        }
#pragma unroll
        for (int j = 0; j < BN / 16; j++) {    // B: BN rows x 16 chunks
            int f = tid + 256 * j; int r = f >> 4, c = f & 15;
            const __half* src = Bm + (long)(colBase + r) * ldb + k0 + c * 8;
            int cs = (c & 8) | ((c & 7) ^ (r & 7));
            uint32_t dst = sB0 + (uint32_t)(buf * BSTG + r * 256 + cs * 16);
            asm volatile("cp.async.cg.shared.global [%0], [%1], 16;" :: "r"(dst), "l"(src));
        }
        asm volatile("cp.async.commit_group;");
    };

    auto compute = [&](int buf) {
        const uint32_t ab = aRow + (uint32_t)(buf * ASTG);
        const uint32_t bb = bRow + (uint32_t)(buf * BSTG);
#pragma unroll
        for (int ks = 0; ks < 8; ks++) {
            uint32_t af[4][4], bf[JN][2];
#pragma unroll
            for (int i = 0; i < 4; i++)
                asm volatile("ldmatrix.sync.aligned.m8n8.x4.shared.b16 {%0,%1,%2,%3}, [%4];"
                    : "=r"(af[i][0]), "=r"(af[i][1]), "=r"(af[i][2]), "=r"(af[i][3])
                    : "r"(ab + i * 4096 + cA[ks]));
#pragma unroll
            for (int p = 0; p < JP; p++)
                asm volatile("ldmatrix.sync.aligned.m8n8.x4.shared.b16 {%0,%1,%2,%3}, [%4];"
                    : "=r"(bf[2 * p][0]), "=r"(bf[2 * p][1]),
                      "=r"(bf[2 * p + 1][0]), "=r"(bf[2 * p + 1][1])
                    : "r"(bb + p * 4096 + cB[ks]));
#pragma unroll
            for (int i = 0; i < 4; i++)
#pragma unroll
                for (int jn = 0; jn < JN; jn++)
                    asm volatile(
                        "mma.sync.aligned.m16n8k16.row.col.f32.f16.f16.f32 "
                        "{%0,%1,%2,%3}, {%4,%5,%6,%7}, {%8,%9}, {%0,%1,%2,%3};"
                        : "+f"(acc[i][jn][0]), "+f"(acc[i][jn][1]),
                          "+f"(acc[i][jn][2]), "+f"(acc[i][jn][3])
                        : "r"(af[i][0]), "r"(af[i][1]), "r"(af[i][2]), "r"(af[i][3]),
                          "r"(bf[jn][0]), "r"(bf[jn][1]));
        }
    };

    const int NTL = K >> 7;
    issue(0, 0);
    for (int kt = 0; kt < NTL; kt++) {
        asm volatile("cp.async.wait_group 0;" ::: "memory");   // chunk kt arrived
        __syncthreads();                                       // + compute(kt-1) done
        if (kt + 1 < NTL) issue(kt + 1, (kt + 1) & 1);         // overlaps compute(kt)
        compute(kt & 1);
    }

    // ---- epilogue ----
#pragma unroll
    for (int i = 0; i < 4; i++) {
        const int row0 = rowBase + wm + i * 16 + g;
#pragma unroll
        for (int jn = 0; jn < JN; jn++) {
            const int col = colBase + wn + jn * 8 + qt * 2;
#pragma unroll
            for (int h = 0; h < 2; h++) {
                const int r = row0 + h * 8;
                float v0 = acc[i][jn][h * 2], v1 = acc[i][jn][h * 2 + 1];
                if (EPI == EPI_BIAS) {
                    v0 += bias[col]; v1 += bias[col + 1];
                } else if (EPI == EPI_BIAS_RELU) {
                    v0 = fmaxf(v0 + bias[col], 0.f);
                    v1 = fmaxf(v1 + bias[col + 1], 0.f);
                }
                if (F16OUT) {
                    *(__half2*)(Ch + (long)r * ldc + col) = __floats2half2_rn(v0, v1);
                } else {
                    float2 o; o.x = v0; o.y = v1;
                    *(float2*)(Cf + (long)r * ldc + col) = o;
                }
            }
        }
    }
}

// ---------------- flash attention (bit-packed mask, strided QKV) -----------
__global__ void __launch_bounds__(256, 1) flash_attn(
    const __half* __restrict__ Qg, const __half* __restrict__ Kg,
    const __half* __restrict__ Vg, int ldq,
    const uint32_t* __restrict__ mbits,
    __half* __restrict__ Og, float scale)
{
    extern __shared__ __align__(16) char sm[];
    const int tid = threadIdx.x, lane = tid & 31, wid = tid >> 5;
    const int g = lane >> 2, qt = lane & 3;
    const int qb = blockIdx.x, bh = blockIdx.y;
    const int b = bh >> 4, h = bh & 15;
    const size_t base = ((size_t)b * S_) * ldq + (size_t)h * DH_;
    const int q0 = qb * 128;

    const uint32_t sQ = smem_u32(sm);
    const uint32_t sK = sQ + 32768;
    const uint32_t sV = sK + 2 * 32768;

    auto ldtile = [&](uint32_t dst, const __half* src) {
#pragma unroll
        for (int j = 0; j < 8; j++) {
            int f = tid + 256 * j, r = f >> 4, c = f & 15;
            int cs = (c & 8) | ((c & 7) ^ (r & 7));
            const __half* s = src + (size_t)r * ldq + c * 8;
            uint32_t d = dst + r * 256 + cs * 16;
            asm volatile("cp.async.cg.shared.global [%0], [%1], 16;" :: "r"(d), "l"(s));
        }
    };

    ldtile(sQ, Qg + base + (size_t)q0 * ldq);
    ldtile(sK, Kg + base);
    ldtile(sV, Vg + base);
    asm volatile("cp.async.commit_group;");
    ldtile(sK + 32768, Kg + base + (size_t)128 * ldq);
    ldtile(sV + 32768, Vg + base + (size_t)128 * ldq);
    asm volatile("cp.async.commit_group;");

    uint32_t afq[8][4];
    {
        asm volatile("cp.async.wait_group 1;" ::: "memory");
        __syncthreads();
        const int ar = wid * 16 + ((lane >> 3) & 1) * 8 + (lane & 7);
#pragma unroll
        for (int ks = 0; ks < 8; ks++) {
            int c = ks * 2 + (lane >> 4);
            int cs = (c & 8) | ((c & 7) ^ (ar & 7));
            asm volatile("ldmatrix.sync.aligned.m8n8.x4.shared.b16 {%0,%1,%2,%3}, [%4];"
                : "=r"(afq[ks][0]), "=r"(afq[ks][1]), "=r"(afq[ks][2]), "=r"(afq[ks][3])
                : "r"(sQ + ar * 256 + cs * 16));
        }
    }

    float acc_o[16][4];
#pragma unroll
    for (int p = 0; p < 16; p++)
#pragma unroll
        for (int u = 0; u < 4; u++) acc_o[p][u] = 0.f;
    float m0 = -3.4e38f, m1 = -3.4e38f, l0 = 0.f, l1 = 0.f;

    const int r0g = q0 + wid * 16 + g;
    const uint32_t* mb0 = mbits + (size_t)r0g * (S_ / 32);
    const uint32_t* mb1 = mbits + (size_t)(r0g + 8) * (S_ / 32);

    for (int t = 0; t < 8; t++) {
        if (t == 7) asm volatile("cp.async.wait_group 0;" ::: "memory");
        else        asm volatile("cp.async.wait_group 1;" ::: "memory");
        __syncthreads();

        const uint32_t kbuf = sK + (t & 1) * 32768;
        const uint32_t vbuf = sV + (t & 1) * 32768;

        // ---- S = Q @ K^T ----
        float sa[16][4];
#pragma unroll
        for (int p = 0; p < 16; p++)
#pragma unroll
            for (int u = 0; u < 4; u++) sa[p][u] = 0.f;
#pragma unroll
        for (int ks = 0; ks < 8; ks++) {
#pragma unroll
            for (int p = 0; p < 8; p++) {
                int br = p * 16 + ((lane >> 4) << 3) + (lane & 7);
                int c = ks * 2 + ((lane >> 3) & 1);
                int cs = (c & 8) | ((c & 7) ^ (br & 7));
                uint32_t b0, b1, b2, b3;
                asm volatile("ldmatrix.sync.aligned.m8n8.x4.shared.b16 {%0,%1,%2,%3}, [%4];"
                    : "=r"(b0), "=r"(b1), "=r"(b2), "=r"(b3)
                    : "r"(kbuf + br * 256 + cs * 16));
                asm volatile(
                    "mma.sync.aligned.m16n8k16.row.col.f32.f16.f16.f32 "
                    "{%0,%1,%2,%3}, {%4,%5,%6,%7}, {%8,%9}, {%0,%1,%2,%3};"
                    : "+f"(sa[2*p][0]), "+f"(sa[2*p][1]), "+f"(sa[2*p][2]), "+f"(sa[2*p][3])
                    : "r"(afq[ks][0]), "r"(afq[ks][1]), "r"(afq[ks][2]), "r"(afq[ks][3]),
                      "r"(b0), "r"(b1));
                asm volatile(
                    "mma.sync.aligned.m16n8k16.row.col.f32.f16.f16.f32 "
                    "{%0,%1,%2,%3}, {%4,%5,%6,%7}, {%8,%9}, {%0,%1,%2,%3};"
                    : "+f"(sa[2*p+1][0]), "+f"(sa[2*p+1][1]), "+f"(sa[2*p+1][2]), "+f"(sa[2*p+1][3])
                    : "r"(afq[ks][0]), "r"(afq[ks][1]), "r"(afq[ks][2]), "r"(afq[ks][3]),
                      "r"(b2), "r"(b3));
            }
        }

        // ---- mask (bits) + scale + online softmax (fp32 exp, R11 proven) ----
        const uint4 w0 = *(const uint4*)(mb0 + t * 4);
        const uint4 w1 = *(const uint4*)(mb1 + t * 4);
        const uint32_t w0a[4] = {w0.x, w0.y, w0.z, w0.w};
        const uint32_t w1a[4] = {w1.x, w1.y, w1.z, w1.w};
        float tm0 = -3.4e38f, tm1 = -3.4e38f;
#pragma unroll
        for (int j = 0; j < 16; j++) {
            const int sh = (j & 3) * 8 + qt * 2, wi = j >> 2;
            sa[j][0] = ((w0a[wi] >> sh)       & 1) ? sa[j][0] * scale : -1e9f;
            sa[j][1] = ((w0a[wi] >> (sh + 1)) & 1) ? sa[j][1] * scale : -1e9f;
            sa[j][2] = ((w1a[wi] >> sh)       & 1) ? sa[j][2] * scale : -1e9f;
            sa[j][3] = ((w1a[wi] >> (sh + 1)) & 1) ? sa[j][3] * scale : -1e9f;
            tm0 = fmaxf(tm0, fmaxf(sa[j][0], sa[j][1]));
            tm1 = fmaxf(tm1, fmaxf(sa[j][2], sa[j][3]));
        }
        tm0 = fmaxf(tm0, __shfl_xor_sync(0xffffffffu, tm0, 1));
        tm0 = fmaxf(tm0, __shfl_xor_sync(0xffffffffu, tm0, 2));
        tm1 = fmaxf(tm1, __shfl_xor_sync(0xffffffffu, tm1, 1));
        tm1 = fmaxf(tm1, __shfl_xor_sync(0xffffffffu, tm1, 2));
        const float mn0 = fmaxf(m0, tm0), mn1 = fmaxf(m1, tm1);
        const float al0 = __expf(m0 - mn0), al1 = __expf(m1 - mn1);
        m0 = mn0; m1 = mn1;

        float ts0 = 0.f, ts1 = 0.f;
        uint32_t pa[8][4];
#pragma unroll
        for (int j2 = 0; j2 < 8; j2++) {
            float p0 = __expf(sa[2*j2][0]   - mn0), p1 = __expf(sa[2*j2][1]   - mn0);
            float p2 = __expf(sa[2*j2][2]   - mn1), p3 = __expf(sa[2*j2][3]   - mn1);
            float p4 = __expf(sa[2*j2+1][0] - mn0), p5 = __expf(sa[2*j2+1][1] - mn0);
            float p6 = __expf(sa[2*j2+1][2] - mn1), p7 = __expf(sa[2*j2+1][3] - mn1);
            ts0 += p0 + p1 + p4 + p5;
            ts1 += p2 + p3 + p6 + p7;
            __half2 q0h = __floats2half2_rn(p0, p1), q1h = __floats2half2_rn(p2, p3);
            __half2 q2h = __floats2half2_rn(p4, p5), q3h = __floats2half2_rn(p6, p7);
            pa[j2][0] = *(uint32_t*)&q0h; pa[j2][1] = *(uint32_t*)&q1h;
            pa[j2][2] = *(uint32_t*)&q2h; pa[j2][3] = *(uint32_t*)&q3h;
        }
        ts0 += __shfl_xor_sync(0xffffffffu, ts0, 1);
        ts0 += __shfl_xor_sync(0xffffffffu, ts0, 2);
        ts1 += __shfl_xor_sync(0xffffffffu, ts1, 1);
        ts1 += __shfl_xor_sync(0xffffffffu, ts1, 2);
        l0 = l0 * al0 + ts0;
        l1 = l1 * al1 + ts1;
#pragma unroll
        for (int p = 0; p < 16; p++) {
            acc_o[p][0] *= al0; acc_o[p][1] *= al0;
            acc_o[p][2] *= al1; acc_o[p][3] *= al1;
        }

        // ---- O += P @ V ----
#pragma unroll
        for (int ks = 0; ks < 8; ks++) {
#pragma unroll
            for (int p = 0; p < 8; p++) {
                int vr = ks * 16 + ((lane >> 3) & 1) * 8 + (lane & 7);
                int c = p * 2 + ((lane >> 4) & 1);
                int cs = (c & 8) | ((c & 7) ^ (vr & 7));
                uint32_t b0, b1, b2, b3;
                asm volatile("ldmatrix.sync.aligned.m8n8.x4.trans.shared.b16 {%0,%1,%2,%3}, [%4];"
                    : "=r"(b0), "=r"(b1), "=r"(b2), "=r"(b3)
                    : "r"(vbuf + vr * 256 + cs * 16));
                asm volatile(
                    "mma.sync.aligned.m16n8k16.row.col.f32.f16.f16.f32 "
                    "{%0,%1,%2,%3}, {%4,%5,%6,%7}, {%8,%9}, {%0,%1,%2,%3};"
                    : "+f"(acc_o[2*p][0]), "+f"(acc_o[2*p][1]), "+f"(acc_o[2*p][2]), "+f"(acc_o[2*p][3])
                    : "r"(pa[ks][0]), "r"(pa[ks][1]), "r"(pa[ks][2]), "r"(pa[ks][3]),
                      "r"(b0), "r"(b1));
                asm volatile(
                    "mma.sync.aligned.m16n8k16.row.col.f32.f16.f16.f32 "
                    "{%0,%1,%2,%3}, {%4,%5,%6,%7}, {%8,%9}, {%0,%1,%2,%3};"
                    : "+f"(acc_o[2*p+1][0]), "+f"(acc_o[2*p+1][1]), "+f"(acc_o[2*p+1][2]), "+f"(acc_o[2*p+1][3])
                    : "r"(pa[ks][0]), "r"(pa[ks][1]), "r"(pa[ks][2]), "r"(pa[ks][3]),
                      "r"(b2), "r"(b3));
            }
        }

        __syncthreads();
        if (t + 2 < 8) {
            ldtile(sK + (t & 1) * 32768, Kg + base + (size_t)(t + 2) * 128 * ldq);
            ldtile(sV + (t & 1) * 32768, Vg + base + (size_t)(t + 2) * 128 * ldq);
            asm volatile("cp.async.commit_group;");
        }
    }

    // ---- epilogue: normalize, write fp16 (O stride = D_) ----
    const float i0 = 1.f / l0, i1 = 1.f / l1;
    const size_t obase = ((size_t)b * S_) * D_ + (size_t)h * DH_;
    __half* orow0 = Og + obase + (size_t)(q0 + wid * 16 + g) * D_;
    __half* orow1 = orow0 + (size_t)8 * D_;
#pragma unroll
    for (int p = 0; p < 16; p++) {
        const int col = p * 8 + qt * 2;
        *(__half2*)(orow0 + col) = __floats2half2_rn(acc_o[p][0] * i0, acc_o[p][1] * i0);
        *(__half2*)(orow1 + col) = __floats2half2_rn(acc_o[p][2] * i1, acc_o[p][3] * i1);
    }
}

// ---------------- prep kernels ---------------------------------------------
__global__ void __launch_bounds__(256) f2h(
    const float4* __restrict__ in, uint4* __restrict__ out, int n8)
{
    int i = blockIdx.x * blockDim.x + threadIdx.x;
    if (i < n8) {
        float4 a = in[2 * i], b = in[2 * i + 1];
        __half2 q0 = __floats2half2_rn(a.x, a.y);
        __half2 q1 = __floats2half2_rn(a.z, a.w);
        __half2 q2 = __floats2half2_rn(b.x, b.y);
        __half2 q3 = __floats2half2_rn(b.z, b.w);
        uint4 u;
        u.x = *(uint32_t*)&q0; u.y = *(uint32_t*)&q1;
        u.z = *(uint32_t*)&q2; u.w = *(uint32_t*)&q3;
        out[i] = u;
    }
}

// pack_mask: one coalesced LDG per thread + ballot.
__global__ void __launch_bounds__(256) pack_mask(
    const int* __restrict__ m, uint32_t* __restrict__ mb)
{
    int gw = (blockIdx.x * blockDim.x + threadIdx.x) >> 5;
    int lane = threadIdx.x & 31;
    int v = m[(size_t)gw * 32 + lane];
    uint32_t bits = __ballot_sync(0xffffffffu, v != 0);
    if (lane == 0) mb[gw] = bits;
}

// ---------------- fused residual + LayerNorm -------------------------------
__device__ __forceinline__ float blk_sum(float v, float* sh)
{
#pragma unroll
    for (int o = 16; o; o >>= 1) v += __shfl_xor_sync(0xffffffffu, v, o);
    const int lane = threadIdx.x & 31, w = threadIdx.x >> 5;
    if (lane == 0) sh[w] = v;
    __syncthreads();
    if (w == 0) {
        float t = (lane < 8) ? sh[lane] : 0.f;
#pragma unroll
        for (int o = 4; o; o >>= 1) t += __shfl_xor_sync(0xffu, t, o);
        if (lane == 0) sh[0] = t;
    }
    __syncthreads();
    const float r = sh[0];
    __syncthreads();
    return r;
}

template <bool DUAL>
__global__ void __launch_bounds__(256) ln_kernel(
    const float* __restrict__ a, const float* __restrict__ b,
    const float* __restrict__ g, const float* __restrict__ be,
    float* __restrict__ out, __half* __restrict__ out_h)
{
    __shared__ float sh[8];
    const int row = blockIdx.x, tid = threadIdx.x;
    const float* pa = a + (size_t)row * D_;
    const float* pb = b + (size_t)row * D_;
    const int c0 = tid * 8;

    float x[8];
    {
        float4 a0 = *(const float4*)&pa[c0], a1 = *(const float4*)&pa[c0 + 4];
        float4 b0 = *(const float4*)&pb[c0], b1 = *(const float4*)&pb[c0 + 4];
        x[0] = a0.x + b0.x; x[1] = a0.y + b0.y; x[2] = a0.z + b0.z; x[3] = a0.w + b0.w;
        x[4] = a1.x + b1.x; x[5] = a1.y + b1.y; x[6] = a1.z + b1.z; x[7] = a1.w + b1.w;
    }
    float s = 0.f;
#pragma unroll
    for (int i = 0; i < 8; i++) s += x[i];
    const float mean = blk_sum(s, sh) * (1.f / D_);

    float vs = 0.f;
#pragma unroll
    for (int i = 0; i < 8; i++) { const float d = x[i] - mean; vs += d * d; }
    const float var = blk_sum(vs, sh) * (1.f / D_);
    const float inv = rsqrtf(var + 1e-5f);

    float o[8];
    float4 g0 = *(const float4*)&g[c0],  g1v = *(const float4*)&g[c0 + 4];
    float4 e0 = *(const float4*)&be[c0], e1v = *(const float4*)&be[c0 + 4];
    o[0] = (x[0] - mean) * inv * g0.x + e0.x;
    o[1] = (x[1] - mean) * inv * g0.y + e0.y;
    o[2] = (x[2] - mean) * inv * g0.z + e0.z;
    o[3] = (x[3] - mean) * inv * g0.w + e0.w;
    o[4] = (x[4] - mean) * inv * g1v.x + e1v.x;
    o[5] = (x[5] - mean) * inv * g1v.y + e1v.y;
    o[6] = (x[6] - mean) * inv * g1v.z + e1v.z;
    o[7] = (x[7] - mean) * inv * g1v.w + e1v.w;

    float* po = out + (size_t)row * D_;
    *(float4*)&po[c0]     = *(float4*)&o[0];
    *(float4*)&po[c0 + 4] = *(float4*)&o[4];
    if (DUAL) {
        __half2* ph = (__half2*)(out_h + (size_t)row * D_ + c0);
        ph[0] = __floats2half2_rn(o[0], o[1]);
        ph[1] = __floats2half2_rn(o[2], o[3]);
        ph[2] = __floats2half2_rn(o[4], o[5]);
        ph[3] = __floats2half2_rn(o[6], o[7]);
    }
}

// ---------------- launch ----------------------------------------------------
extern "C" void kernel_launch(void* const* d_in, const int* in_sizes, int n_in,
                              void* d_out, int out_size)
{
    const float* x    = (const float*)d_in[0];
    const int*   mask = (const int*)  d_in[1];
    const float* Wq = (const float*)d_in[2];  const float* bq = (const float*)d_in[3];
    const float* Wk = (const float*)d_in[4];  const float* bk = (const float*)d_in[5];
    const float* Wv = (const float*)d_in[6];  const float* bv = (const float*)d_in[7];
    const float* Wo = (const float*)d_in[8];  const float* bo = (const float*)d_in[9];
    const float* W1 = (const float*)d_in[10]; const float* b1 = (const float*)d_in[11];
    const float* W2 = (const float*)d_in[12]; const float* b2 = (const float*)d_in[13];
    const float* g1 = (const float*)d_in[14]; const float* be1 = (const float*)d_in[15];
    const float* g2 = (const float*)d_in[16]; const float* be2 = (const float*)d_in[17];
    float* out = (float*)d_out;

    float *ko, *x1, *bqkv;
    uint32_t* mb;
    __half *hx, *hqkv, *hao, *hx1, *hw, *hh;
    cudaGetSymbolAddress((void**)&ko,   g_k);
    cudaGetSymbolAddress((void**)&x1,   g_v);
    cudaGetSymbolAddress((void**)&bqkv, g_bqkv);
    cudaGetSymbolAddress((void**)&mb,   g_mb);
    cudaGetSymbolAddress((void**)&hx,   h_x);
    cudaGetSymbolAddress((void**)&hqkv, h_qkv);
    cudaGetSymbolAddress((void**)&hao,  h_ao);
    cudaGetSymbolAddress((void**)&hx1,  h_x1);
    cudaGetSymbolAddress((void**)&hw,   h_w);
    cudaGetSymbolAddress((void**)&hh,   h_h);

    __half* hWqkv = hw;                               // Wq|Wk|Wv contiguous
    __half* hWo = hw + (size_t)3 * D_ * D_;
    __half* hW1 = hw + (size_t)4 * D_ * D_;
    __half* hW2 = hW1 + (size_t)FF_ * D_;

    const int SMEM256 = 2 * (128 * 256 + 256 * 256);  // 196608
    const int SMEM128 = 2 * (128 * 256 + 128 * 256);  // 131072
    const int SMEM_FA = 5 * 32768;                    // 163840
    cudaFuncSetAttribute(hgemm<256, EPI_BIAS, true>,
                         cudaFuncAttributeMaxDynamicSharedMemorySize, SMEM256);
    cudaFuncSetAttribute(hgemm<256, EPI_BIAS_RELU, true>,
                         cudaFuncAttributeMaxDynamicSharedMemorySize, SMEM256);
    cudaFuncSetAttribute(hgemm<128, EPI_BIAS, false>,
                         cudaFuncAttributeMaxDynamicSharedMemorySize, SMEM128);
    cudaFuncSetAttribute(flash_attn,
                         cudaFuncAttributeMaxDynamicSharedMemorySize, SMEM_FA);

    const float scale = 0.08838834764831843f;  // 1/sqrt(128)

    // ---- prep: fp16 conversions, bias concat, mask pack ----
    auto cv = [&](const float* src, __half* dst, size_t n) {
        int n8 = (int)(n / 8);
        f2h<<<(n8 + 255) / 256, 256>>>((const float4*)src, (uint4*)dst, n8);
    };
    cv(x,  hx,               (size_t)NTOK * D_);
    cv(Wq, hWqkv,            (size_t)D_ * D_);
    cv(Wk, hWqkv + (size_t)D_ * D_,     (size_t)D_ * D_);
    cv(Wv, hWqkv + (size_t)2 * D_ * D_, (size_t)D_ * D_);
    cv(Wo, hWo,              (size_t)D_ * D_);
    cv(W1, hW1,              (size_t)FF_ * D_);
    cv(W2, hW2,              (size_t)D_ * FF_);
    cudaMemcpyAsync(bqkv,          bq, D_ * sizeof(float), cudaMemcpyDeviceToDevice);
    cudaMemcpyAsync(bqkv + D_,     bk, D_ * sizeof(float), cudaMemcpyDeviceToDevice);
    cudaMemcpyAsync(bqkv + 2 * D_, bv, D_ * sizeof(float), cudaMemcpyDeviceToDevice);
    pack_mask<<<(S_ * S_) / 256, 256>>>(mask, mb);

    // ---- fused QKV projection: [8192, 6144] (BN=256) ----
    dim3 gqkv(LDQKV / 256, NTOK / 128, 1);
    hgemm<256, EPI_BIAS, true><<<gqkv, 256, SMEM256>>>(
        hx, D_, hWqkv, D_, hqkv, LDQKV, D_, bqkv);

    // ---- fused attention (Q at +0, K at +D_, V at +2*D_ elements) ----
    flash_attn<<<dim3(S_ / 128, B_ * H_), 256, SMEM_FA>>>(
        hqkv, hqkv + D_, hqkv + 2 * D_, LDQKV, mb, hao, scale);

    // ---- output projection (BN=128 -> 1024 CTAs, kills wave tail), LN1 ----
    dim3 gproj128(D_ / 128, NTOK / 128, 1);
    hgemm<128, EPI_BIAS, false><<<gproj128, 256, SMEM128>>>(
        hao, D_, hWo, D_, ko, D_, D_, bo);
    ln_kernel<true><<<NTOK, 256>>>(ko, x, g1, be1, x1, hx1);

    // ---- FFN ----
    dim3 gff1(FF_ / 256, NTOK / 128, 1);
    hgemm<256, EPI_BIAS_RELU, true><<<gff1, 256, SMEM256>>>(
        hx1, D_, hW1, D_, hh, FF_, D_, b1);
    hgemm<128, EPI_BIAS, false><<<gproj128, 256, SMEM128>>>(
        hh, FF_, hW2, FF_, ko, D_, FF_, b2);

    // ---- LN2 -> out ----
    ln_kernel<false><<<NTOK, 256>>>(ko, x1, g2, be2, out, nullptr);
}

// round 14
// speedup vs baseline: 1.0198x; 1.0075x over previous
#include <cuda_runtime.h>
#include <cuda_fp16.h>
#include <cstdint>

#define B_   8
#define S_   1024
#define D_   2048
#define H_   16
#define DH_  128
#define FF_  8192
#define NTOK (B_*S_)   // 8192
#define LDQKV (3*D_)   // 6144

// ---------------- scratch ----------------
__device__ float    g_k[(size_t)NTOK * D_];           // fp32: Wo out / FFN2 out
__device__ float    g_v[(size_t)NTOK * D_];           // fp32: x1 exact
__device__ float    g_bqkv[3 * D_];                   // concat bias
__device__ uint32_t g_mb[(size_t)S_ * (S_ / 32)];     // bit-packed mask
__device__ __half   h_x  [(size_t)NTOK * D_];
__device__ __half   h_qkv[(size_t)NTOK * LDQKV];      // fused Q|K|V
__device__ __half   h_ao [(size_t)NTOK * D_];
__device__ __half   h_x1 [(size_t)NTOK * D_];
__device__ __half   h_w  [(size_t)(4 * D_ * D_ + 2 * FF_ * D_)];
__device__ __half   h_h  [(size_t)NTOK * FF_];        // fp16 FFN hidden

enum { EPI_NONE = 0, EPI_BIAS = 1, EPI_BIAS_RELU = 2 };

__device__ __forceinline__ uint32_t smem_u32(const void* p) {
    uint32_t a;
    asm("{ .reg .u64 t; cvta.to.shared.u64 t, %1; cvt.u32.u64 %0, t; }" : "=r"(a) : "l"(p));
    return a;
}

// ---------------- fp16 mma.sync GEMM (NT; A,B fp16; fp32 accum) ------------
// BK=128 chunks (256B smem rows), 2 stages, ONE sync/chunk. BN = 256 or 128.
template <int BN, int EPI, bool F16OUT>
__global__ void __launch_bounds__(256, 1) hgemm(
    const __half* __restrict__ A, int lda,
    const __half* __restrict__ Bm, int ldb,
    void* __restrict__ Cv, int ldc,
    int K, const float* __restrict__ bias)
{
    extern __shared__ __align__(16) char sm[];
    const int tid = threadIdx.x, lane = tid & 31, wid = tid >> 5;

    __half* Ch = (__half*)Cv;
    float*  Cf = (float*)Cv;

    const int rowBase = blockIdx.y * 128;
    const int colBase = blockIdx.x * BN;

    constexpr int WN  = BN / 4;      // warp N tile (64 or 32)
    constexpr int JN  = WN / 8;      // 8 or 4
    constexpr int JP  = JN / 2;      // ldmatrix x4 pairs for B (4 or 2)
    constexpr int ASTG = 128 * 256;  // bytes per A stage (256B rows, 128 halves)
    constexpr int BSTG = BN * 256;
    const uint32_t sA0 = smem_u32(sm);
    const uint32_t sB0 = sA0 + 2 * ASTG;

    const int wm = (wid & 1) * 64;
    const int wn = (wid >> 1) * WN;
    const int g  = lane >> 2, qt = lane & 3;

    // ldmatrix per-lane addressing (256B rows; swizzle cs=(c&8)|((c&7)^(r&7)))
    const int aR = wm + ((lane >> 3) & 1) * 8 + (lane & 7);
    const int aHi = lane >> 4;               // 0/1 k-half within 32B pair
    const uint32_t aRow = sA0 + (uint32_t)aR * 256;
    const int aS = aR & 7;
    const int bR = wn + ((lane >> 4) << 3) + (lane & 7);
    const int bHi = (lane >> 3) & 1;
    const uint32_t bRow = sB0 + (uint32_t)bR * 256;
    const int bS = bR & 7;
    uint32_t cA[8], cB[8];
#pragma unroll
    for (int ks = 0; ks < 8; ks++) {
        int ca = 2 * ks + aHi, cb = 2 * ks + bHi;
        cA[ks] = (uint32_t)(((ca & 8) | ((ca & 7) ^ aS)) * 16);
        cB[ks] = (uint32_t)(((cb & 8) | ((cb & 7) ^ bS)) * 16);
    }

    float acc[4][JN][4];
#pragma unroll
    for (int i = 0; i < 4; i++)
#pragma unroll
        for (int j = 0; j < JN; j++)
#pragma unroll
            for (int u = 0; u < 4; u++) acc[i][j][u] = 0.f;

    auto issue = [&](int kt, int buf) {
        const int k0 = kt << 7;
#pragma unroll
        for (int j = 0; j < 8; j++) {          // A: 128 rows x 16 chunks
            int f = tid + 256 * j; int r = f >> 4, c = f & 15;
            const __half* src = A + (long)(rowBase + r) * lda + k0 + c * 8;
            int cs = (c & 8) | ((c & 7) ^ (r & 7));
            uint32_t dst = sA0 + (uint32_t)(buf * ASTG + r * 256 + cs * 16);
            asm volatile("cp.async.cg.shared.global [%0], [%1], 16;" :: "r"(dst), "l"(src));
        }
#pragma unroll
        for (int j = 0; j < BN / 16; j++) {    // B: BN rows x 16 chunks
            int f = tid + 256 * j; int r = f >> 4, c = f & 15;
            const __half* src = Bm + (long)(colBase + r) * ldb + k0 + c * 8;
            int cs = (c & 8) | ((c & 7) ^ (r & 7));
            uint32_t dst = sB0 + (uint32_t)(buf * BSTG + r * 256 + cs * 16);
            asm volatile("cp.async.cg.shared.global [%0], [%1], 16;" :: "r"(dst), "l"(src));
        }
        asm volatile("cp.async.commit_group;");
    };

    auto compute = [&](int buf) {
        const uint32_t ab = aRow + (uint32_t)(buf * ASTG);
        const uint32_t bb = bRow + (uint32_t)(buf * BSTG);
#pragma unroll
        for (int ks = 0; ks < 8; ks++) {
            uint32_t af[4][4], bf[JN][2];
#pragma unroll
            for (int i = 0; i < 4; i++)
                asm volatile("ldmatrix.sync.aligned.m8n8.x4.shared.b16 {%0,%1,%2,%3}, [%4];"
                    : "=r"(af[i][0]), "=r"(af[i][1]), "=r"(af[i][2]), "=r"(af[i][3])
                    : "r"(ab + i * 4096 + cA[ks]));
#pragma unroll
            for (int p = 0; p < JP; p++)
                asm volatile("ldmatrix.sync.aligned.m8n8.x4.shared.b16 {%0,%1,%2,%3}, [%4];"
                    : "=r"(bf[2 * p][0]), "=r"(bf[2 * p][1]),
                      "=r"(bf[2 * p + 1][0]), "=r"(bf[2 * p + 1][1])
                    : "r"(bb + p * 4096 + cB[ks]));
#pragma unroll
            for (int i = 0; i < 4; i++)
#pragma unroll
                for (int jn = 0; jn < JN; jn++)
                    asm volatile(
                        "mma.sync.aligned.m16n8k16.row.col.f32.f16.f16.f32 "
                        "{%0,%1,%2,%3}, {%4,%5,%6,%7}, {%8,%9}, {%0,%1,%2,%3};"
                        : "+f"(acc[i][jn][0]), "+f"(acc[i][jn][1]),
                          "+f"(acc[i][jn][2]), "+f"(acc[i][jn][3])
                        : "r"(af[i][0]), "r"(af[i][1]), "r"(af[i][2]), "r"(af[i][3]),
                          "r"(bf[jn][0]), "r"(bf[jn][1]));
        }
    };

    const int NTL = K >> 7;
    issue(0, 0);
    for (int kt = 0; kt < NTL; kt++) {
        asm volatile("cp.async.wait_group 0;" ::: "memory");   // chunk kt arrived
        __syncthreads();                                       // + compute(kt-1) done
        if (kt + 1 < NTL) issue(kt + 1, (kt + 1) & 1);         // overlaps compute(kt)
        compute(kt & 1);
    }

    // ---- epilogue ----
#pragma unroll
    for (int i = 0; i < 4; i++) {
        const int row0 = rowBase + wm + i * 16 + g;
#pragma unroll
        for (int jn = 0; jn < JN; jn++) {
            const int col = colBase + wn + jn * 8 + qt * 2;
#pragma unroll
            for (int h = 0; h < 2; h++) {
                const int r = row0 + h * 8;
                float v0 = acc[i][jn][h * 2], v1 = acc[i][jn][h * 2 + 1];
                if (EPI == EPI_BIAS) {
                    v0 += bias[col]; v1 += bias[col + 1];
                } else if (EPI == EPI_BIAS_RELU) {
                    v0 = fmaxf(v0 + bias[col], 0.f);
                    v1 = fmaxf(v1 + bias[col + 1], 0.f);
                }
                if (F16OUT) {
                    *(__half2*)(Ch + (long)r * ldc + col) = __floats2half2_rn(v0, v1);
                } else {
                    float2 o; o.x = v0; o.y = v1;
                    *(float2*)(Cf + (long)r * ldc + col) = o;
                }
            }
        }
    }
}

// ---------------- flash attention (bit-packed mask, strided QKV) -----------
__global__ void __launch_bounds__(256, 1) flash_attn(
    const __half* __restrict__ Qg, const __half* __restrict__ Kg,
    const __half* __restrict__ Vg, int ldq,
    const uint32_t* __restrict__ mbits,
    __half* __restrict__ Og, float scale)
{
    extern __shared__ __align__(16) char sm[];
    const int tid = threadIdx.x, lane = tid & 31, wid = tid >> 5;
    const int g = lane >> 2, qt = lane & 3;
    const int qb = blockIdx.x, bh = blockIdx.y;
    const int b = bh >> 4, h = bh & 15;
    const size_t base = ((size_t)b * S_) * ldq + (size_t)h * DH_;
    const int q0 = qb * 128;

    const uint32_t sQ = smem_u32(sm);
    const uint32_t sK = sQ + 32768;
    const uint32_t sV = sK + 2 * 32768;

    auto ldtile = [&](uint32_t dst, const __half* src) {
#pragma unroll
        for (int j = 0; j < 8; j++) {
            int f = tid + 256 * j, r = f >> 4, c = f & 15;
            int cs = (c & 8) | ((c & 7) ^ (r & 7));
            const __half* s = src + (size_t)r * ldq + c * 8;
            uint32_t d = dst + r * 256 + cs * 16;
            asm volatile("cp.async.cg.shared.global [%0], [%1], 16;" :: "r"(d), "l"(s));
        }
    };

    ldtile(sQ, Qg + base + (size_t)q0 * ldq);
    ldtile(sK, Kg + base);
    ldtile(sV, Vg + base);
    asm volatile("cp.async.commit_group;");
    ldtile(sK + 32768, Kg + base + (size_t)128 * ldq);
    ldtile(sV + 32768, Vg + base + (size_t)128 * ldq);
    asm volatile("cp.async.commit_group;");

    uint32_t afq[8][4];
    {
        asm volatile("cp.async.wait_group 1;" ::: "memory");
        __syncthreads();
        const int ar = wid * 16 + ((lane >> 3) & 1) * 8 + (lane & 7);
#pragma unroll
        for (int ks = 0; ks < 8; ks++) {
            int c = ks * 2 + (lane >> 4);
            int cs = (c & 8) | ((c & 7) ^ (ar & 7));
            asm volatile("ldmatrix.sync.aligned.m8n8.x4.shared.b16 {%0,%1,%2,%3}, [%4];"
                : "=r"(afq[ks][0]), "=r"(afq[ks][1]), "=r"(afq[ks][2]), "=r"(afq[ks][3])
                : "r"(sQ + ar * 256 + cs * 16));
        }
    }

    float acc_o[16][4];
#pragma unroll
    for (int p = 0; p < 16; p++)
#pragma unroll
        for (int u = 0; u < 4; u++) acc_o[p][u] = 0.f;
    float m0 = -3.4e38f, m1 = -3.4e38f, l0 = 0.f, l1 = 0.f;

    const int r0g = q0 + wid * 16 + g;
    const uint32_t* mb0 = mbits + (size_t)r0g * (S_ / 32);
    const uint32_t* mb1 = mbits + (size_t)(r0g + 8) * (S_ / 32);

    for (int t = 0; t < 8; t++) {
        if (t == 7) asm volatile("cp.async.wait_group 0;" ::: "memory");
        else        asm volatile("cp.async.wait_group 1;" ::: "memory");
        __syncthreads();

        const uint32_t kbuf = sK + (t & 1) * 32768;
        const uint32_t vbuf = sV + (t & 1) * 32768;

        // ---- S = Q @ K^T ----
        float sa[16][4];
#pragma unroll
        for (int p = 0; p < 16; p++)
#pragma unroll
            for (int u = 0; u < 4; u++) sa[p][u] = 0.f;
#pragma unroll
        for (int ks = 0; ks < 8; ks++) {
#pragma unroll
            for (int p = 0; p < 8; p++) {
                int br = p * 16 + ((lane >> 4) << 3) + (lane & 7);
                int c = ks * 2 + ((lane >> 3) & 1);
                int cs = (c & 8) | ((c & 7) ^ (br & 7));
                uint32_t b0, b1, b2, b3;
                asm volatile("ldmatrix.sync.aligned.m8n8.x4.shared.b16 {%0,%1,%2,%3}, [%4];"
                    : "=r"(b0), "=r"(b1), "=r"(b2), "=r"(b3)
                    : "r"(kbuf + br * 256 + cs * 16));
                asm volatile(
                    "mma.sync.aligned.m16n8k16.row.col.f32.f16.f16.f32 "
                    "{%0,%1,%2,%3}, {%4,%5,%6,%7}, {%8,%9}, {%0,%1,%2,%3};"
                    : "+f"(sa[2*p][0]), "+f"(sa[2*p][1]), "+f"(sa[2*p][2]), "+f"(sa[2*p][3])
                    : "r"(afq[ks][0]), "r"(afq[ks][1]), "r"(afq[ks][2]), "r"(afq[ks][3]),
                      "r"(b0), "r"(b1));
                asm volatile(
                    "mma.sync.aligned.m16n8k16.row.col.f32.f16.f16.f32 "
                    "{%0,%1,%2,%3}, {%4,%5,%6,%7}, {%8,%9}, {%0,%1,%2,%3};"
                    : "+f"(sa[2*p+1][0]), "+f"(sa[2*p+1][1]), "+f"(sa[2*p+1][2]), "+f"(sa[2*p+1][3])
                    : "r"(afq[ks][0]), "r"(afq[ks][1]), "r"(afq[ks][2]), "r"(afq[ks][3]),
                      "r"(b2), "r"(b3));
            }
        }

        // ---- mask (bits) + scale + online softmax ----
        const uint4 w0 = *(const uint4*)(mb0 + t * 4);
        const uint4 w1 = *(const uint4*)(mb1 + t * 4);
        const uint32_t w0a[4] = {w0.x, w0.y, w0.z, w0.w};
        const uint32_t w1a[4] = {w1.x, w1.y, w1.z, w1.w};
        float tm0 = -3.4e38f, tm1 = -3.4e38f;
#pragma unroll
        for (int j = 0; j < 16; j++) {
            const int sh = (j & 3) * 8 + qt * 2, wi = j >> 2;
            sa[j][0] = ((w0a[wi] >> sh)       & 1) ? sa[j][0] * scale : -1e9f;
            sa[j][1] = ((w0a[wi] >> (sh + 1)) & 1) ? sa[j][1] * scale : -1e9f;
            sa[j][2] = ((w1a[wi] >> sh)       & 1) ? sa[j][2] * scale : -1e9f;
            sa[j][3] = ((w1a[wi] >> (sh + 1)) & 1) ? sa[j][3] * scale : -1e9f;
            tm0 = fmaxf(tm0, fmaxf(sa[j][0], sa[j][1]));
            tm1 = fmaxf(tm1, fmaxf(sa[j][2], sa[j][3]));
        }
        tm0 = fmaxf(tm0, __shfl_xor_sync(0xffffffffu, tm0, 1));
        tm0 = fmaxf(tm0, __shfl_xor_sync(0xffffffffu, tm0, 2));
        tm1 = fmaxf(tm1, __shfl_xor_sync(0xffffffffu, tm1, 1));
        tm1 = fmaxf(tm1, __shfl_xor_sync(0xffffffffu, tm1, 2));
        const float mn0 = fmaxf(m0, tm0), mn1 = fmaxf(m1, tm1);
        const float al0 = __expf(m0 - mn0), al1 = __expf(m1 - mn1);
        m0 = mn0; m1 = mn1;

        float ts0 = 0.f, ts1 = 0.f;
        uint32_t pa[8][4];
#pragma unroll
        for (int j2 = 0; j2 < 8; j2++) {
            float p0 = __expf(sa[2*j2][0]   - mn0), p1 = __expf(sa[2*j2][1]   - mn0);
            float p2 = __expf(sa[2*j2][2]   - mn1), p3 = __expf(sa[2*j2][3]   - mn1);
            float p4 = __expf(sa[2*j2+1][0] - mn0), p5 = __expf(sa[2*j2+1][1] - mn0);
            float p6 = __expf(sa[2*j2+1][2] - mn1), p7 = __expf(sa[2*j2+1][3] - mn1);
            ts0 += p0 + p1 + p4 + p5;
            ts1 += p2 + p3 + p6 + p7;
            __half2 q0h = __floats2half2_rn(p0, p1), q1h = __floats2half2_rn(p2, p3);
            __half2 q2h = __floats2half2_rn(p4, p5), q3h = __floats2half2_rn(p6, p7);
            pa[j2][0] = *(uint32_t*)&q0h; pa[j2][1] = *(uint32_t*)&q1h;
            pa[j2][2] = *(uint32_t*)&q2h; pa[j2][3] = *(uint32_t*)&q3h;
        }
        ts0 += __shfl_xor_sync(0xffffffffu, ts0, 1);
        ts0 += __shfl_xor_sync(0xffffffffu, ts0, 2);
        ts1 += __shfl_xor_sync(0xffffffffu, ts1, 1);
        ts1 += __shfl_xor_sync(0xffffffffu, ts1, 2);
        l0 = l0 * al0 + ts0;
        l1 = l1 * al1 + ts1;
#pragma unroll
        for (int p = 0; p < 16; p++) {
            acc_o[p][0] *= al0; acc_o[p][1] *= al0;
            acc_o[p][2] *= al1; acc_o[p][3] *= al1;
        }

        // ---- O += P @ V ----
#pragma unroll
        for (int ks = 0; ks < 8; ks++) {
#pragma unroll
            for (int p = 0; p < 8; p++) {
                int vr = ks * 16 + ((lane >> 3) & 1) * 8 + (lane & 7);
                int c = p * 2 + ((lane >> 4) & 1);
                int cs = (c & 8) | ((c & 7) ^ (vr & 7));
                uint32_t b0, b1, b2, b3;
                asm volatile("ldmatrix.sync.aligned.m8n8.x4.trans.shared.b16 {%0,%1,%2,%3}, [%4];"
                    : "=r"(b0), "=r"(b1), "=r"(b2), "=r"(b3)
                    : "r"(vbuf + vr * 256 + cs * 16));
                asm volatile(
                    "mma.sync.aligned.m16n8k16.row.col.f32.f16.f16.f32 "
                    "{%0,%1,%2,%3}, {%4,%5,%6,%7}, {%8,%9}, {%0,%1,%2,%3};"
                    : "+f"(acc_o[2*p][0]), "+f"(acc_o[2*p][1]), "+f"(acc_o[2*p][2]), "+f"(acc_o[2*p][3])
                    : "r"(pa[ks][0]), "r"(pa[ks][1]), "r"(pa[ks][2]), "r"(pa[ks][3]),
                      "r"(b0), "r"(b1));
                asm volatile(
                    "mma.sync.aligned.m16n8k16.row.col.f32.f16.f16.f32 "
                    "{%0,%1,%2,%3}, {%4,%5,%6,%7}, {%8,%9}, {%0,%1,%2,%3};"
                    : "+f"(acc_o[2*p+1][0]), "+f"(acc_o[2*p+1][1]), "+f"(acc_o[2*p+1][2]), "+f"(acc_o[2*p+1][3])
                    : "r"(pa[ks][0]), "r"(pa[ks][1]), "r"(pa[ks][2]), "r"(pa[ks][3]),
                      "r"(b2), "r"(b3));
            }
        }

        __syncthreads();
        if (t + 2 < 8) {
            ldtile(sK + (t & 1) * 32768, Kg + base + (size_t)(t + 2) * 128 * ldq);
            ldtile(sV + (t & 1) * 32768, Vg + base + (size_t)(t + 2) * 128 * ldq);
            asm volatile("cp.async.commit_group;");
        }
    }

    // ---- epilogue: normalize, write fp16 (O stride = D_) ----
    const float i0 = 1.f / l0, i1 = 1.f / l1;
    const size_t obase = ((size_t)b * S_) * D_ + (size_t)h * DH_;
    __half* orow0 = Og + obase + (size_t)(q0 + wid * 16 + g) * D_;
    __half* orow1 = orow0 + (size_t)8 * D_;
#pragma unroll
    for (int p = 0; p < 16; p++) {
        const int col = p * 8 + qt * 2;
        *(__half2*)(orow0 + col) = __floats2half2_rn(acc_o[p][0] * i0, acc_o[p][1] * i0);
        *(__half2*)(orow1 + col) = __floats2half2_rn(acc_o[p][2] * i1, acc_o[p][3] * i1);
    }
}

// ---------------- batched prep: all 7 fp32->fp16 conversions, ONE launch ----
// Segments (uint4 units of 8 halves): x | Wq | Wk | Wv | Wo | W1 | W2
// SX=2097152, SW=524288 (x4), SF=2097152 (x2); total = 8388608 = 32768 CTAs.
#define SX_ ((size_t)NTOK * D_ / 8)
#define SW_ ((size_t)D_ * D_ / 8)
#define SF_ ((size_t)FF_ * D_ / 8)
__global__ void __launch_bounds__(256) f2h_all(
    const float4* __restrict__ x,
    const float4* __restrict__ wq, const float4* __restrict__ wk,
    const float4* __restrict__ wv, const float4* __restrict__ wo,
    const float4* __restrict__ w1, const float4* __restrict__ w2,
    uint4* __restrict__ ox, uint4* __restrict__ ow)
{
    const size_t i = (size_t)blockIdx.x * 256 + threadIdx.x;
    const float4* src; uint4* dst; size_t j;
    if (i < SX_)                    { src = x;  dst = ox;            j = i; }
    else if (i < SX_ + SW_)         { src = wq; dst = ow;            j = i - SX_; }
    else if (i < SX_ + 2 * SW_)     { src = wk; dst = ow + SW_;      j = i - SX_ - SW_; }
    else if (i < SX_ + 3 * SW_)     { src = wv; dst = ow + 2 * SW_;  j = i - SX_ - 2 * SW_; }
    else if (i < SX_ + 4 * SW_)     { src = wo; dst = ow + 3 * SW_;  j = i - SX_ - 3 * SW_; }
    else if (i < SX_ + 4 * SW_ + SF_) { src = w1; dst = ow + 4 * SW_; j = i - SX_ - 4 * SW_; }
    else                            { src = w2; dst = ow + 4 * SW_ + SF_; j = i - SX_ - 4 * SW_ - SF_; }

    float4 a = src[2 * j], b = src[2 * j + 1];
    __half2 q0 = __floats2half2_rn(a.x, a.y);
    __half2 q1 = __floats2half2_rn(a.z, a.w);
    __half2 q2 = __floats2half2_rn(b.x, b.y);
    __half2 q3 = __floats2half2_rn(b.z, b.w);
    uint4 u;
    u.x = *(uint32_t*)&q0; u.y = *(uint32_t*)&q1;
    u.z = *(uint32_t*)&q2; u.w = *(uint32_t*)&q3;
    dst[j] = u;
}

// pack_mask: one coalesced LDG per thread + ballot.
__global__ void __launch_bounds__(256) pack_mask(
    const int* __restrict__ m, uint32_t* __restrict__ mb)
{
    int gw = (blockIdx.x * blockDim.x + threadIdx.x) >> 5;
    int lane = threadIdx.x & 31;
    int v = m[(size_t)gw * 32 + lane];
    uint32_t bits = __ballot_sync(0xffffffffu, v != 0);
    if (lane == 0) mb[gw] = bits;
}

// ---------------- fused residual + LayerNorm -------------------------------
__device__ __forceinline__ float blk_sum(float v, float* sh)
{
#pragma unroll
    for (int o = 16; o; o >>= 1) v += __shfl_xor_sync(0xffffffffu, v, o);
    const int lane = threadIdx.x & 31, w = threadIdx.x >> 5;
    if (lane == 0) sh[w] = v;
    __syncthreads();
    if (w == 0) {
        float t = (lane < 8) ? sh[lane] : 0.f;
#pragma unroll
        for (int o = 4; o; o >>= 1) t += __shfl_xor_sync(0xffu, t, o);
        if (lane == 0) sh[0] = t;
    }
    __syncthreads();
    const float r = sh[0];
    __syncthreads();
    return r;
}

template <bool DUAL>
__global__ void __launch_bounds__(256) ln_kernel(
    const float* __restrict__ a, const float* __restrict__ b,
    const float* __restrict__ g, const float* __restrict__ be,
    float* __restrict__ out, __half* __restrict__ out_h)
{
    __shared__ float sh[8];
    const int row = blockIdx.x, tid = threadIdx.x;
    const float* pa = a + (size_t)row * D_;
    const float* pb = b + (size_t)row * D_;
    const int c0 = tid * 8;

    float x[8];
    {
        float4 a0 = *(const float4*)&pa[c0], a1 = *(const float4*)&pa[c0 + 4];
        float4 b0 = *(const float4*)&pb[c0], b1 = *(const float4*)&pb[c0 + 4];
        x[0] = a0.x + b0.x; x[1] = a0.y + b0.y; x[2] = a0.z + b0.z; x[3] = a0.w + b0.w;
        x[4] = a1.x + b1.x; x[5] = a1.y + b1.y; x[6] = a1.z + b1.z; x[7] = a1.w + b1.w;
    }
    float s = 0.f;
#pragma unroll
    for (int i = 0; i < 8; i++) s += x[i];
    const float mean = blk_sum(s, sh) * (1.f / D_);

    float vs = 0.f;
#pragma unroll
    for (int i = 0; i < 8; i++) { const float d = x[i] - mean; vs += d * d; }
    const float var = blk_sum(vs, sh) * (1.f / D_);
    const float inv = rsqrtf(var + 1e-5f);

    float o[8];
    float4 g0 = *(const float4*)&g[c0],  g1v = *(const float4*)&g[c0 + 4];
    float4 e0 = *(const float4*)&be[c0], e1v = *(const float4*)&be[c0 + 4];
    o[0] = (x[0] - mean) * inv * g0.x + e0.x;
    o[1] = (x[1] - mean) * inv * g0.y + e0.y;
    o[2] = (x[2] - mean) * inv * g0.z + e0.z;
    o[3] = (x[3] - mean) * inv * g0.w + e0.w;
    o[4] = (x[4] - mean) * inv * g1v.x + e1v.x;
    o[5] = (x[5] - mean) * inv * g1v.y + e1v.y;
    o[6] = (x[6] - mean) * inv * g1v.z + e1v.z;
    o[7] = (x[7] - mean) * inv * g1v.w + e1v.w;

    float* po = out + (size_t)row * D_;
    *(float4*)&po[c0]     = *(float4*)&o[0];
    *(float4*)&po[c0 + 4] = *(float4*)&o[4];
    if (DUAL) {
        __half2* ph = (__half2*)(out_h + (size_t)row * D_ + c0);
        ph[0] = __floats2half2_rn(o[0], o[1]);
        ph[1] = __floats2half2_rn(o[2], o[3]);
        ph[2] = __floats2half2_rn(o[4], o[5]);
        ph[3] = __floats2half2_rn(o[6], o[7]);
    }
}

// ---------------- launch ----------------------------------------------------
extern "C" void kernel_launch(void* const* d_in, const int* in_sizes, int n_in,
                              void* d_out, int out_size)
{
    const float* x    = (const float*)d_in[0];
    const int*   mask = (const int*)  d_in[1];
    const float* Wq = (const float*)d_in[2];  const float* bq = (const float*)d_in[3];
    const float* Wk = (const float*)d_in[4];  const float* bk = (const float*)d_in[5];
    const float* Wv = (const float*)d_in[6];  const float* bv = (const float*)d_in[7];
    const float* Wo = (const float*)d_in[8];  const float* bo = (const float*)d_in[9];
    const float* W1 = (const float*)d_in[10]; const float* b1 = (const float*)d_in[11];
    const float* W2 = (const float*)d_in[12]; const float* b2 = (const float*)d_in[13];
    const float* g1 = (const float*)d_in[14]; const float* be1 = (const float*)d_in[15];
    const float* g2 = (const float*)d_in[16]; const float* be2 = (const float*)d_in[17];
    float* out = (float*)d_out;

    float *ko, *x1, *bqkv;
    uint32_t* mb;
    __half *hx, *hqkv, *hao, *hx1, *hw, *hh;
    cudaGetSymbolAddress((void**)&ko,   g_k);
    cudaGetSymbolAddress((void**)&x1,   g_v);
    cudaGetSymbolAddress((void**)&bqkv, g_bqkv);
    cudaGetSymbolAddress((void**)&mb,   g_mb);
    cudaGetSymbolAddress((void**)&hx,   h_x);
    cudaGetSymbolAddress((void**)&hqkv, h_qkv);
    cudaGetSymbolAddress((void**)&hao,  h_ao);
    cudaGetSymbolAddress((void**)&hx1,  h_x1);
    cudaGetSymbolAddress((void**)&hw,   h_w);
    cudaGetSymbolAddress((void**)&hh,   h_h);

    __half* hWqkv = hw;                               // Wq|Wk|Wv contiguous
    __half* hWo = hw + (size_t)3 * D_ * D_;
    __half* hW1 = hw + (size_t)4 * D_ * D_;
    __half* hW2 = hW1 + (size_t)FF_ * D_;

    const int SMEM256 = 2 * (128 * 256 + 256 * 256);  // 196608
    const int SMEM128 = 2 * (128 * 256 + 128 * 256);  // 131072
    const int SMEM_FA = 5 * 32768;                    // 163840
    cudaFuncSetAttribute(hgemm<256, EPI_BIAS, true>,
                         cudaFuncAttributeMaxDynamicSharedMemorySize, SMEM256);
    cudaFuncSetAttribute(hgemm<256, EPI_BIAS_RELU, true>,
                         cudaFuncAttributeMaxDynamicSharedMemorySize, SMEM256);
    cudaFuncSetAttribute(hgemm<128, EPI_BIAS, false>,
                         cudaFuncAttributeMaxDynamicSharedMemorySize, SMEM128);
    cudaFuncSetAttribute(flash_attn,
                         cudaFuncAttributeMaxDynamicSharedMemorySize, SMEM_FA);

    const float scale = 0.08838834764831843f;  // 1/sqrt(128)

    // ---- prep: single batched conversion + bias concat + mask pack ----
    const int prep_ctas = (int)((SX_ + 4 * SW_ + 2 * SF_) / 256);  // 32768
    f2h_all<<<prep_ctas, 256>>>(
        (const float4*)x, (const float4*)Wq, (const float4*)Wk,
        (const float4*)Wv, (const float4*)Wo, (const float4*)W1,
        (const float4*)W2, (uint4*)hx, (uint4*)hw);
    cudaMemcpyAsync(bqkv,          bq, D_ * sizeof(float), cudaMemcpyDeviceToDevice);
    cudaMemcpyAsync(bqkv + D_,     bk, D_ * sizeof(float), cudaMemcpyDeviceToDevice);
    cudaMemcpyAsync(bqkv + 2 * D_, bv, D_ * sizeof(float), cudaMemcpyDeviceToDevice);
    pack_mask<<<(S_ * S_) / 256, 256>>>(mask, mb);

    // ---- fused QKV projection: [8192, 6144] (BN=256) ----
    dim3 gqkv(LDQKV / 256, NTOK / 128, 1);
    hgemm<256, EPI_BIAS, true><<<gqkv, 256, SMEM256>>>(
        hx, D_, hWqkv, D_, hqkv, LDQKV, D_, bqkv);

    // ---- fused attention (Q at +0, K at +D_, V at +2*D_ elements) ----
    flash_attn<<<dim3(S_ / 128, B_ * H_), 256, SMEM_FA>>>(
        hqkv, hqkv + D_, hqkv + 2 * D_, LDQKV, mb, hao, scale);

    // ---- output projection (BN=128 -> 1024 CTAs), LN1 ----
    dim3 gproj128(D_ / 128, NTOK / 128, 1);
    hgemm<128, EPI_BIAS, false><<<gproj128, 256, SMEM128>>>(
        hao, D_, hWo, D_, ko, D_, D_, bo);
    ln_kernel<true><<<NTOK, 256>>>(ko, x, g1, be1, x1, hx1);

    // ---- FFN ----
    dim3 gff1(FF_ / 256, NTOK / 128, 1);
    hgemm<256, EPI_BIAS_RELU, true><<<gff1, 256, SMEM256>>>(
        hx1, D_, hW1, D_, hh, FF_, D_, b1);
    hgemm<128, EPI_BIAS, false><<<gproj128, 256, SMEM128>>>(
        hh, FF_, hW2, FF_, ko, D_, FF_, b2);

    // ---- LN2 -> out ----
    ln_kernel<false><<<NTOK, 256>>>(ko, x1, g2, be2, out, nullptr);
}